// round 2
// baseline (speedup 1.0000x reference)
#include <cuda_runtime.h>
#include <cuda_bf16.h>

// Problem constants (fixed by setup_inputs)
#define B_   8
#define T_   2048
#define C_   256
#define L_   32
#define DQ_  512
#define NW_  2017      // T - 32 + 1
#define STOT_ 2045     // T - 4 + 1  (s = w + 4j range)

// Scratch (device globals: no allocations allowed)
__device__ float g_part1[8 * 65536];   // k-split partials for enc1
__device__ float g_part2[8 * 65536];   // k-split partials for enc2
__device__ float g_enc1[65536];        // (B*L, C)
__device__ float g_enc2[65536];
__device__ int   g_labels[B_ * T_];

// ---------------------------------------------------------------------------
// Kernel A1: partial GEMMs  enc = query @ W  (K split into 8 ranges of 64)
// grid (8 ksplit, 32 l), block 256 (thread = c). 8 b-rows per block.
// ---------------------------------------------------------------------------
__global__ void gemm_part(const float* __restrict__ query,
                          const float* __restrict__ W1,
                          const float* __restrict__ W2) {
    __shared__ float qsT[64 * 8];   // qsT[d][bb]
    const int l   = blockIdx.y;
    const int k0  = blockIdx.x * 64;
    const int tid = threadIdx.x;

    for (int i = tid; i < 512; i += 256) {
        int d = i >> 3, bb = i & 7;
        qsT[d * 8 + bb] = query[(bb * L_ + l) * DQ_ + k0 + d];
    }
    __syncthreads();

    const int c = tid;
    float a1[8], a2[8];
#pragma unroll
    for (int i = 0; i < 8; ++i) { a1[i] = 0.f; a2[i] = 0.f; }

#pragma unroll 4
    for (int d = 0; d < 64; ++d) {
        float w1 = W1[(k0 + d) * C_ + c];
        float w2 = W2[(k0 + d) * C_ + c];
        float4 qa = *(const float4*)&qsT[d * 8];
        float4 qb = *(const float4*)&qsT[d * 8 + 4];
        a1[0] += qa.x * w1; a1[1] += qa.y * w1; a1[2] += qa.z * w1; a1[3] += qa.w * w1;
        a1[4] += qb.x * w1; a1[5] += qb.y * w1; a1[6] += qb.z * w1; a1[7] += qb.w * w1;
        a2[0] += qa.x * w2; a2[1] += qa.y * w2; a2[2] += qa.z * w2; a2[3] += qa.w * w2;
        a2[4] += qb.x * w2; a2[5] += qb.y * w2; a2[6] += qb.z * w2; a2[7] += qb.w * w2;
    }

    const int kidx = blockIdx.x;
#pragma unroll
    for (int bb = 0; bb < 8; ++bb) {
        int row = bb * L_ + l;
        g_part1[kidx * 65536 + row * C_ + c] = a1[bb];
        g_part2[kidx * 65536 + row * C_ + c] = a2[bb];
    }
}

// ---------------------------------------------------------------------------
// Kernel A2: deterministic reduce of k-split partials + bias
// ---------------------------------------------------------------------------
__global__ void gemm_reduce(const float* __restrict__ b1,
                            const float* __restrict__ b2) {
    int i = blockIdx.x * 256 + threadIdx.x;   // 0..65535
    int c = i & (C_ - 1);
    float s1 = b1[c], s2 = b2[c];
#pragma unroll
    for (int k = 0; k < 8; ++k) {
        s1 += g_part1[k * 65536 + i];
        s2 += g_part2[k * 65536 + i];
    }
    g_enc1[i] = s1;
    g_enc2[i] = s2;
}

// ---------------------------------------------------------------------------
// Kernel B: clip_labels[b,t] = argmax_l  vis[b,t,:] . enc1[b,l,:]
// grid (8 b, 16 t-tiles), block 128 (thread = t). enc1[b] in smem (32 KB).
// All lanes read identical smem addresses per step -> broadcast LDS.
// ---------------------------------------------------------------------------
__global__ void labels_kernel(const float* __restrict__ vis) {
    __shared__ float es[L_ * C_];   // 32 KB
    const int b   = blockIdx.x;
    const int t0  = blockIdx.y * 128;
    const int tid = threadIdx.x;

    for (int i = tid; i < L_ * C_; i += 128)
        es[i] = g_enc1[b * (L_ * C_) + i];
    __syncthreads();

    const int t = t0 + tid;
    const float4* v4 = (const float4*)(vis + ((size_t)b * T_ + t) * C_);

    float acc[L_];
#pragma unroll
    for (int l = 0; l < L_; ++l) acc[l] = 0.f;

    for (int c0 = 0; c0 < C_ / 4; ++c0) {
        float4 v = v4[c0];
#pragma unroll
        for (int l = 0; l < L_; ++l) {
            float4 e = *(const float4*)&es[l * C_ + c0 * 4];
            acc[l] += v.x * e.x + v.y * e.y + v.z * e.z + v.w * e.w;
        }
    }

    // argmax, first (lowest l) max on ties — matches jnp.argmax
    float best = acc[0];
    int   bi   = 0;
#pragma unroll
    for (int l = 1; l < L_; ++l)
        if (acc[l] > best) { best = acc[l]; bi = l; }
    g_labels[b * T_ + t] = bi;
}

// ---------------------------------------------------------------------------
// Kernel D: out[b,w,j,c] = enc2[b, maj4(labels[b, s..s+3]), c]
//                          * (vis[b,s,c]+..+vis[b,s+3,c]) / 4,   s = w + 4j.
// Compute per (b, s, c4) once, scatter to all (w, j) with w = s - 4j.
// grid (512 s-tiles, 8 b), block 256 = 4 s-groups x 64 c4-threads.
// enc2[b] staged in smem. All stores are coalesced STG.128.
// ---------------------------------------------------------------------------
__global__ void out_kernel(const float* __restrict__ vis,
                           float* __restrict__ out) {
    __shared__ float4 e2s[L_ * C_ / 4];   // 32 KB
    const int b   = blockIdx.y;
    const int tid = threadIdx.x;

    const float4* e2g = (const float4*)g_enc2 + b * (L_ * C_ / 4);
    for (int i = tid; i < L_ * C_ / 4; i += 256) e2s[i] = e2g[i];
    __syncthreads();

    const int s = blockIdx.x * 4 + (tid >> 6);
    if (s >= STOT_) return;
    const int c4 = tid & 63;

    // majority of 4 consecutive labels; ties -> smallest label value
    const int* lab = g_labels + b * T_ + s;
    int l0 = lab[0], l1 = lab[1], l2 = lab[2], l3 = lab[3];
    int n0 = (l0 == l1) + (l0 == l2) + (l0 == l3);
    int n1 = (l1 == l0) + (l1 == l2) + (l1 == l3);
    int n2 = (l2 == l0) + (l2 == l1) + (l2 == l3);
    int n3 = (l3 == l0) + (l3 == l1) + (l3 == l2);
    int maj = l0, bc = n0;
    if (n1 > bc || (n1 == bc && l1 < maj)) { bc = n1; maj = l1; }
    if (n2 > bc || (n2 == bc && l2 < maj)) { bc = n2; maj = l2; }
    if (n3 > bc || (n3 == bc && l3 < maj)) { bc = n3; maj = l3; }

    const float4* vp = (const float4*)vis + ((size_t)b * T_ + s) * 64 + c4;
    float4 v0 = vp[0];
    float4 v1 = vp[64];
    float4 v2 = vp[128];
    float4 v3 = vp[192];
    float4 e  = e2s[maj * 64 + c4];

    float4 g;
    g.x = e.x * (v0.x + v1.x + v2.x + v3.x) * 0.25f;
    g.y = e.y * (v0.y + v1.y + v2.y + v3.y) * 0.25f;
    g.z = e.z * (v0.z + v1.z + v2.z + v3.z) * 0.25f;
    g.w = e.w * (v0.w + v1.w + v2.w + v3.w) * 0.25f;

    const int jhi = min(7, s >> 2);
    const int jlo = (s > NW_ - 1) ? ((s - (NW_ - 1) + 3) >> 2) : 0;
    float4* o = (float4*)out;
#pragma unroll
    for (int j = jlo; j <= jhi; ++j) {
        int w = s - 4 * j;
        o[(((size_t)b * NW_ + w) * 8 + j) * 64 + c4] = g;
    }
}

// ---------------------------------------------------------------------------
extern "C" void kernel_launch(void* const* d_in, const int* in_sizes, int n_in,
                              void* d_out, int out_size) {
    (void)in_sizes; (void)n_in; (void)out_size;
    const float* vis   = (const float*)d_in[0];
    const float* query = (const float*)d_in[1];
    const float* W1    = (const float*)d_in[2];
    const float* b1    = (const float*)d_in[3];
    const float* W2    = (const float*)d_in[4];
    const float* b2    = (const float*)d_in[5];

    gemm_part  <<<dim3(8, 32),  256>>>(query, W1, W2);
    gemm_reduce<<<256,          256>>>(b1, b2);
    labels_kernel<<<dim3(8, 16), 128>>>(vis);
    out_kernel <<<dim3(512, 8), 256>>>(vis, (float*)d_out);
}

// round 4
// speedup vs baseline: 1.2493x; 1.2493x over previous
#include <cuda_runtime.h>
#include <cuda_bf16.h>

// Problem constants (fixed by setup_inputs)
#define B_   8
#define T_   2048
#define C_   256
#define L_   32
#define DQ_  512
#define NW_  2017      // T - 32 + 1
#define STOT_ 2045     // T - 4 + 1  (s = w + 4j range)

// Scratch (device globals: no allocations allowed)
__device__ float g_part1[8 * 65536];   // k-split partials for enc1
__device__ float g_part2[8 * 65536];   // k-split partials for enc2
__device__ float g_enc1[65536];        // (B*L, C)
__device__ float g_enc2[65536];
__device__ int   g_labels[B_ * T_];

// ---------------------------------------------------------------------------
// Kernel A1: partial GEMMs  enc = query @ W  (K split into 8 ranges of 64)
// grid (8 ksplit, 32 l), block 256 (thread = c). 8 b-rows per block.
// ---------------------------------------------------------------------------
__global__ void gemm_part(const float* __restrict__ query,
                          const float* __restrict__ W1,
                          const float* __restrict__ W2) {
    __shared__ float qsT[64 * 8];   // qsT[d][bb]
    const int l   = blockIdx.y;
    const int k0  = blockIdx.x * 64;
    const int tid = threadIdx.x;

    for (int i = tid; i < 512; i += 256) {
        int d = i >> 3, bb = i & 7;
        qsT[d * 8 + bb] = query[(bb * L_ + l) * DQ_ + k0 + d];
    }
    __syncthreads();

    const int c = tid;
    float a1[8], a2[8];
#pragma unroll
    for (int i = 0; i < 8; ++i) { a1[i] = 0.f; a2[i] = 0.f; }

#pragma unroll 4
    for (int d = 0; d < 64; ++d) {
        float w1 = W1[(k0 + d) * C_ + c];
        float w2 = W2[(k0 + d) * C_ + c];
        float4 qa = *(const float4*)&qsT[d * 8];
        float4 qb = *(const float4*)&qsT[d * 8 + 4];
        a1[0] += qa.x * w1; a1[1] += qa.y * w1; a1[2] += qa.z * w1; a1[3] += qa.w * w1;
        a1[4] += qb.x * w1; a1[5] += qb.y * w1; a1[6] += qb.z * w1; a1[7] += qb.w * w1;
        a2[0] += qa.x * w2; a2[1] += qa.y * w2; a2[2] += qa.z * w2; a2[3] += qa.w * w2;
        a2[4] += qb.x * w2; a2[5] += qb.y * w2; a2[6] += qb.z * w2; a2[7] += qb.w * w2;
    }

    const int kidx = blockIdx.x;
#pragma unroll
    for (int bb = 0; bb < 8; ++bb) {
        int row = bb * L_ + l;
        g_part1[kidx * 65536 + row * C_ + c] = a1[bb];
        g_part2[kidx * 65536 + row * C_ + c] = a2[bb];
    }
}

// ---------------------------------------------------------------------------
// Kernel A2: deterministic reduce of k-split partials + bias
// ---------------------------------------------------------------------------
__global__ void gemm_reduce(const float* __restrict__ b1,
                            const float* __restrict__ b2) {
    int i = blockIdx.x * 256 + threadIdx.x;   // 0..65535
    int c = i & (C_ - 1);
    float s1 = b1[c], s2 = b2[c];
#pragma unroll
    for (int k = 0; k < 8; ++k) {
        s1 += g_part1[k * 65536 + i];
        s2 += g_part2[k * 65536 + i];
    }
    g_enc1[i] = s1;
    g_enc2[i] = s2;
}

// ---------------------------------------------------------------------------
// Kernel B v2: clip_labels[b,t] = argmax_l  vis[b,t,:] . enc1[b,l,:]
// grid (8 b, 32 t-tiles of 64), block 256 = 64 t x 4 c-chunks of 64.
// Warp layout: wid>>1 = chunk (uniform per warp -> broadcast LDS on enc1),
// p = (wid&1)*32+lane = t-slot. Cross-chunk reduce through the SAME 32KB
// smem buffer (enc1 no longer needed), layout [l*4+ch][t] (conflict-free
// writes, <=4-way reads), then argmax with shfl combine over 4 l-groups.
// ---------------------------------------------------------------------------
__global__ void labels_kernel(const float* __restrict__ vis) {
    __shared__ __align__(16) float sbuf[8192];   // 32 KB: enc1[b], then partials
    const int b     = blockIdx.x;
    const int tbase = blockIdx.y * 64;
    const int tid   = threadIdx.x;
    const int lane  = tid & 31;
    const int wid   = tid >> 5;
    const int chunk = wid >> 1;                  // 0..3  (c in [chunk*64, +64))
    const int p     = ((wid & 1) << 5) | lane;   // 0..63 t-slot
    const int t     = tbase + p;

    // stage enc1[b] (32 KB)
    {
        const float4* src = (const float4*)g_enc1 + b * 2048;
        float4* dst = (float4*)sbuf;
        for (int i = tid; i < 2048; i += 256) dst[i] = src[i];
    }
    __syncthreads();

    const float4* v4 = (const float4*)(vis + ((size_t)b * T_ + t) * C_) + chunk * 16;
    const float4* e4 = (const float4*)sbuf + chunk * 16;

    float acc[L_];
#pragma unroll
    for (int l = 0; l < L_; ++l) acc[l] = 0.f;

#pragma unroll 4
    for (int c0 = 0; c0 < 16; ++c0) {
        float4 v = v4[c0];
#pragma unroll
        for (int l = 0; l < L_; ++l) {
            float4 e = e4[l * 64 + c0];          // uniform across warp -> broadcast
            acc[l] += v.x * e.x + v.y * e.y + v.z * e.z + v.w * e.w;
        }
    }

    // everyone done reading enc1 -> reuse sbuf for partials
    __syncthreads();
#pragma unroll
    for (int l = 0; l < L_; ++l)
        sbuf[(l * 4 + chunk) * 64 + p] = acc[l];  // lanes p contiguous: conflict-free
    __syncthreads();

    // reduce: thread = (t2 = tid>>2, lg = tid&3 handling 8 l's)
    const int t2 = tid >> 2;
    const int lg = tid & 3;
    float best = -3.0e38f;
    int   bi   = 0;
#pragma unroll
    for (int li = 0; li < 8; ++li) {
        int l = lg * 8 + li;
        float s = sbuf[(l * 4 + 0) * 64 + t2]
                + sbuf[(l * 4 + 1) * 64 + t2]
                + sbuf[(l * 4 + 2) * 64 + t2]
                + sbuf[(l * 4 + 3) * 64 + t2];
        if (s > best) { best = s; bi = l; }
    }
    // combine the 4 l-groups (lanes differing in bits 0..1)
#pragma unroll
    for (int off = 1; off <= 2; off <<= 1) {
        float ov = __shfl_xor_sync(0xffffffffu, best, off);
        int   oi = __shfl_xor_sync(0xffffffffu, bi,   off);
        if (ov > best || (ov == best && oi < bi)) { best = ov; bi = oi; }
    }
    if (lg == 0) g_labels[b * T_ + tbase + t2] = bi;
}

// ---------------------------------------------------------------------------
// Kernel D v2: out[b,w,j,c] = enc2[b, maj4(labels[b,s..s+3]), c]
//              * (vis[b,s,c]+..+vis[b,s+3,c]) / 4,  s = w + 4j.
// grid (64 s-tiles of 32, 8 b), block 256 = 4 s-groups x 64 c4.
// Each s-group walks 8 consecutive s with a register sliding window of 4
// vis rows (1 new row per step). enc2[b] staged once per block (amortized
// over 32 s -> staging traffic 16 MB instead of 134 MB). Stores coalesced.
// ---------------------------------------------------------------------------
__global__ void out_kernel(const float* __restrict__ vis,
                           float* __restrict__ out) {
    __shared__ float4 e2s[2048];   // 32 KB
    const int b   = blockIdx.y;
    const int tid = threadIdx.x;

    const float4* e2g = (const float4*)g_enc2 + b * 2048;
    for (int i = tid; i < 2048; i += 256) e2s[i] = e2g[i];
    __syncthreads();

    const int sgrp = tid >> 6;                 // 0..3
    const int c4   = tid & 63;
    const int s0   = blockIdx.x * 32 + sgrp * 8;

    // prefetch the 11 labels this s-group can touch (uniform across c4 lanes)
    int la[11];
    const int* lab = g_labels + b * T_ + s0;
#pragma unroll
    for (int k = 0; k < 11; ++k)
        la[k] = (s0 + k < T_) ? lab[k] : 0;

    const float4* vp = (const float4*)vis + ((size_t)b * T_ + s0) * 64 + c4;
    float4 w0 = vp[0], w1 = vp[64], w2 = vp[128], w3 = vp[192];
    float4* o = (float4*)out;

#pragma unroll
    for (int i = 0; i < 8; ++i) {
        const int s = s0 + i;
        if (s >= STOT_) break;

        // majority of labels[s..s+3]; ties -> smallest label value
        int l0 = la[i], l1 = la[i + 1], l2 = la[i + 2], l3 = la[i + 3];
        int n0 = (l0 == l1) + (l0 == l2) + (l0 == l3);
        int n1 = (l1 == l0) + (l1 == l2) + (l1 == l3);
        int n2 = (l2 == l0) + (l2 == l1) + (l2 == l3);
        int n3 = (l3 == l0) + (l3 == l1) + (l3 == l2);
        int maj = l0, bc = n0;
        if (n1 > bc || (n1 == bc && l1 < maj)) { bc = n1; maj = l1; }
        if (n2 > bc || (n2 == bc && l2 < maj)) { bc = n2; maj = l2; }
        if (n3 > bc || (n3 == bc && l3 < maj)) { bc = n3; maj = l3; }

        float4 e = e2s[maj * 64 + c4];
        float4 g;
        g.x = e.x * (w0.x + w1.x + w2.x + w3.x) * 0.25f;
        g.y = e.y * (w0.y + w1.y + w2.y + w3.y) * 0.25f;
        g.z = e.z * (w0.z + w1.z + w2.z + w3.z) * 0.25f;
        g.w = e.w * (w0.w + w1.w + w2.w + w3.w) * 0.25f;

        const int jhi = min(7, s >> 2);
        const int jlo = (s > NW_ - 1) ? ((s - (NW_ - 1) + 3) >> 2) : 0;
#pragma unroll
        for (int j = jlo; j <= jhi; ++j) {
            int w = s - 4 * j;
            o[(((size_t)b * NW_ + w) * 8 + j) * 64 + c4] = g;
        }

        // slide window: drop row s, load row s+4 (for next s)
        w0 = w1; w1 = w2; w2 = w3;
        if (i < 7 && s + 4 < T_) w3 = vp[(i + 4) * 64];
    }
}

// ---------------------------------------------------------------------------
extern "C" void kernel_launch(void* const* d_in, const int* in_sizes, int n_in,
                              void* d_out, int out_size) {
    (void)in_sizes; (void)n_in; (void)out_size;
    const float* vis   = (const float*)d_in[0];
    const float* query = (const float*)d_in[1];
    const float* W1    = (const float*)d_in[2];
    const float* b1    = (const float*)d_in[3];
    const float* W2    = (const float*)d_in[4];
    const float* b2    = (const float*)d_in[5];

    gemm_part    <<<dim3(8, 32), 256>>>(query, W1, W2);
    gemm_reduce  <<<256,         256>>>(b1, b2);
    labels_kernel<<<dim3(8, 32), 256>>>(vis);
    out_kernel   <<<dim3(64, 8), 256>>>(vis, (float*)d_out);
}